// round 4
// baseline (speedup 1.0000x reference)
#include <cuda_runtime.h>
#include <math.h>

// Gating: x[B=8,S=8192,H=512] f32, gate_w[E=4,H], gate_b[E]
// Outputs concatenated in d_out (float32):
//   [0, 4T)        sparse_logits  (softmax over top-2, zeros elsewhere)
//   [4T, 6T)       indices (top-2 expert ids, as float)
//   [6T, 10T)      gate_logit (raw logits)
// T = B*S = 65536.

#define HIDDEN 512
#define NEXP 4
#define NTOK 65536
#define TPW 4              // tokens per warp
#define WARPS 8            // warps per block
#define TOK_PER_BLOCK (TPW * WARPS)

// ---- packed f32x2 helpers (sm_103a) ----
__device__ __forceinline__ unsigned long long pk2(float lo, float hi) {
    unsigned long long r;
    asm("mov.b64 %0, {%1, %2};" : "=l"(r) : "f"(lo), "f"(hi));
    return r;
}
__device__ __forceinline__ void fma2(unsigned long long& d,
                                     unsigned long long a,
                                     unsigned long long b) {
    asm("fma.rn.f32x2 %0, %1, %2, %0;" : "+l"(d) : "l"(a), "l"(b));
}
__device__ __forceinline__ float unpk_sum(unsigned long long v) {
    float lo, hi;
    asm("mov.b64 {%0, %1}, %2;" : "=f"(lo), "=f"(hi) : "l"(v));
    return lo + hi;
}

__global__ __launch_bounds__(256) void gating_kernel(
    const float* __restrict__ x,
    const float* __restrict__ gate_w,
    const float* __restrict__ gate_b,
    float* __restrict__ out)
{
    // gate_w staged in shared: 4 experts x 512 floats = 8KB, as float4
    __shared__ float4 sgw[NEXP][HIDDEN / 4];
    __shared__ float sgb[NEXP];

    int tid = threadIdx.x;
    for (int i = tid; i < NEXP * (HIDDEN / 4); i += 256) {
        ((float4*)sgw)[i] = ((const float4*)gate_w)[i];
    }
    if (tid < NEXP) sgb[tid] = gate_b[tid];
    __syncthreads();

    int warpid = tid >> 5;
    int lane   = tid & 31;
    int tbase  = blockIdx.x * TOK_PER_BLOCK + warpid * TPW;

    const float4* xr = (const float4*)(x + (size_t)tbase * HIDDEN);

    // packed accumulator per (token, expert)
    unsigned long long acc[TPW][NEXP];
#pragma unroll
    for (int t = 0; t < TPW; t++)
#pragma unroll
        for (int e = 0; e < NEXP; e++) acc[t][e] = 0ull;

#pragma unroll
    for (int i = 0; i < 4; i++) {
        int h = lane + i * 32;
        // 4 LDS.128 per chunk, reused across TPW tokens
        float4 w0 = sgw[0][h];
        float4 w1 = sgw[1][h];
        float4 w2 = sgw[2][h];
        float4 w3 = sgw[3][h];
        unsigned long long w0a = pk2(w0.x, w0.y), w0b = pk2(w0.z, w0.w);
        unsigned long long w1a = pk2(w1.x, w1.y), w1b = pk2(w1.z, w1.w);
        unsigned long long w2a = pk2(w2.x, w2.y), w2b = pk2(w2.z, w2.w);
        unsigned long long w3a = pk2(w3.x, w3.y), w3b = pk2(w3.z, w3.w);
#pragma unroll
        for (int t = 0; t < TPW; t++) {
            float4 v = xr[t * (HIDDEN / 4) + h];
            unsigned long long va = pk2(v.x, v.y), vb = pk2(v.z, v.w);
            fma2(acc[t][0], va, w0a); fma2(acc[t][0], vb, w0b);
            fma2(acc[t][1], va, w1a); fma2(acc[t][1], vb, w1b);
            fma2(acc[t][2], va, w2a); fma2(acc[t][2], vb, w2b);
            fma2(acc[t][3], va, w3a); fma2(acc[t][3], vb, w3b);
        }
    }

    // collapse packed halves, then butterfly-reduce all 16 scalars
    float a[TPW][NEXP];
#pragma unroll
    for (int t = 0; t < TPW; t++)
#pragma unroll
        for (int e = 0; e < NEXP; e++) a[t][e] = unpk_sum(acc[t][e]);

#pragma unroll
    for (int o = 16; o > 0; o >>= 1) {
#pragma unroll
        for (int t = 0; t < TPW; t++)
#pragma unroll
            for (int e = 0; e < NEXP; e++)
                a[t][e] += __shfl_xor_sync(0xFFFFFFFFu, a[t][e], o);
    }

    // lanes 0..TPW-1 each handle one token's epilogue (all lanes hold all sums)
    if (lane < TPW) {
        int t = lane;
        int token = tbase + t;

        float l[NEXP];
#pragma unroll
        for (int e = 0; e < NEXP; e++) l[e] = a[t][e] + sgb[e];

        // gate_logit (raw logits)
        float4* glog = (float4*)(out + (size_t)6 * NTOK);
        glog[token] = make_float4(l[0], l[1], l[2], l[3]);

        // top-2 (stable: earlier index wins ties, matching jax top_k)
        int i0 = 0; float m0 = l[0];
#pragma unroll
        for (int e = 1; e < NEXP; e++) { if (l[e] > m0) { m0 = l[e]; i0 = e; } }
        int i1 = -1; float m1 = -INFINITY;
#pragma unroll
        for (int e = 0; e < NEXP; e++) {
            if (e != i0 && l[e] > m1) { m1 = l[e]; i1 = e; }
        }

        // softmax over {m0, m1} (others are -inf -> 0)
        float e1 = __expf(m1 - m0);
        float inv = 1.0f / (1.0f + e1);
        float p0 = inv;
        float p1 = e1 * inv;

        float sp[NEXP] = {0.f, 0.f, 0.f, 0.f};
        sp[i0] = p0;
        sp[i1] = p1;
        float4* spv = (float4*)out;
        spv[token] = make_float4(sp[0], sp[1], sp[2], sp[3]);

        // indices as float
        float2* idx = (float2*)(out + (size_t)4 * NTOK);
        idx[token] = make_float2((float)i0, (float)i1);
    }
}

extern "C" void kernel_launch(void* const* d_in, const int* in_sizes, int n_in,
                              void* d_out, int out_size)
{
    const float* x      = (const float*)d_in[0];
    const float* gate_w = (const float*)d_in[1];
    const float* gate_b = (const float*)d_in[2];
    float* out = (float*)d_out;

    // 65536 tokens, 32 tokens per block -> 2048 blocks
    gating_kernel<<<NTOK / TOK_PER_BLOCK, 256>>>(x, gate_w, gate_b, out);
}

// round 5
// speedup vs baseline: 1.2685x; 1.2685x over previous
#include <cuda_runtime.h>
#include <math.h>

// Gating: x[B=8,S=8192,H=512] f32, gate_w[E=4,H], gate_b[E]
// Outputs concatenated in d_out (float32):
//   [0, 4T)   sparse_logits   [4T,6T) indices(float)   [6T,10T) gate_logit
// T = B*S = 65536.

#define HIDDEN 512
#define NEXP 4
#define NTOK 65536
#define TPW 2              // tokens per warp
#define WARPS 8            // warps per block
#define TOK_PER_BLOCK (TPW * WARPS)   // 16

__global__ __launch_bounds__(256) void gating_kernel(
    const float* __restrict__ x,
    const float* __restrict__ gate_w,
    const float* __restrict__ gate_b,
    float* __restrict__ out)
{
    __shared__ float4 sgw[NEXP][HIDDEN / 4];   // 8KB
    __shared__ float sgb[NEXP];

    int tid    = threadIdx.x;
    int warpid = tid >> 5;
    int lane   = tid & 31;
    int tbase  = blockIdx.x * TOK_PER_BLOCK + warpid * TPW;

    const float4* xr = (const float4*)(x + (size_t)tbase * HIDDEN);

    // ---- front-batch ALL x loads (8 LDG.128, MLP_p1=8), before the barrier ----
    float4 v[TPW][4];
#pragma unroll
    for (int t = 0; t < TPW; t++)
#pragma unroll
        for (int i = 0; i < 4; i++)
            v[t][i] = xr[t * (HIDDEN / 4) + lane + i * 32];

    // stage weights while x loads are in flight
    for (int i = tid; i < NEXP * (HIDDEN / 4); i += 256) {
        ((float4*)sgw)[i] = ((const float4*)gate_w)[i];
    }
    if (tid < NEXP) sgb[tid] = gate_b[tid];
    __syncthreads();

    float a[TPW][NEXP];
#pragma unroll
    for (int t = 0; t < TPW; t++)
#pragma unroll
        for (int e = 0; e < NEXP; e++) a[t][e] = 0.f;

#pragma unroll
    for (int i = 0; i < 4; i++) {
        int h = lane + i * 32;
        float4 w0 = sgw[0][h];
        float4 w1 = sgw[1][h];
        float4 w2 = sgw[2][h];
        float4 w3 = sgw[3][h];
#pragma unroll
        for (int t = 0; t < TPW; t++) {
            float4 vv = v[t][i];
            a[t][0] += vv.x * w0.x + vv.y * w0.y + vv.z * w0.z + vv.w * w0.w;
            a[t][1] += vv.x * w1.x + vv.y * w1.y + vv.z * w1.z + vv.w * w1.w;
            a[t][2] += vv.x * w2.x + vv.y * w2.y + vv.z * w2.z + vv.w * w2.w;
            a[t][3] += vv.x * w3.x + vv.y * w3.y + vv.z * w3.z + vv.w * w3.w;
        }
    }

    // butterfly-reduce 8 scalars across the warp
#pragma unroll
    for (int o = 16; o > 0; o >>= 1) {
#pragma unroll
        for (int t = 0; t < TPW; t++)
#pragma unroll
            for (int e = 0; e < NEXP; e++)
                a[t][e] += __shfl_xor_sync(0xFFFFFFFFu, a[t][e], o);
    }

    // lanes 0..TPW-1 each finish one token
    if (lane < TPW) {
        int t = lane;
        int token = tbase + t;

        float l[NEXP];
#pragma unroll
        for (int e = 0; e < NEXP; e++) l[e] = a[t][e] + sgb[e];

        // gate_logit (raw logits)
        float4* glog = (float4*)(out + (size_t)6 * NTOK);
        glog[token] = make_float4(l[0], l[1], l[2], l[3]);

        // top-2 (earlier index wins ties, matching jax top_k)
        int i0 = 0; float m0 = l[0];
#pragma unroll
        for (int e = 1; e < NEXP; e++) { if (l[e] > m0) { m0 = l[e]; i0 = e; } }
        int i1 = -1; float m1 = -INFINITY;
#pragma unroll
        for (int e = 0; e < NEXP; e++) {
            if (e != i0 && l[e] > m1) { m1 = l[e]; i1 = e; }
        }

        // softmax over {m0, m1}
        float e1 = __expf(m1 - m0);
        float inv = 1.0f / (1.0f + e1);

        float sp[NEXP] = {0.f, 0.f, 0.f, 0.f};
        sp[i0] = inv;
        sp[i1] = e1 * inv;
        float4* spv = (float4*)out;
        spv[token] = make_float4(sp[0], sp[1], sp[2], sp[3]);

        float2* idx = (float2*)(out + (size_t)4 * NTOK);
        idx[token] = make_float2((float)i0, (float)i1);
    }
}

extern "C" void kernel_launch(void* const* d_in, const int* in_sizes, int n_in,
                              void* d_out, int out_size)
{
    const float* x      = (const float*)d_in[0];
    const float* gate_w = (const float*)d_in[1];
    const float* gate_b = (const float*)d_in[2];
    float* out = (float*)d_out;

    // 65536 tokens, 16 tokens per block -> 4096 blocks
    gating_kernel<<<NTOK / TOK_PER_BLOCK, 256>>>(x, gate_w, gate_b, out);
}